// round 11
// baseline (speedup 1.0000x reference)
#include <cuda_runtime.h>
#include <cuda_bf16.h>
#include <math.h>
#include <cstdint>

// ============================================================================
// BiDirectionalSymplecticLayer — fused persistent kernel, reg-pipelined.
// BM=128 rows/CTA, 512 threads. All 8 gradient evals local; H/G tiles in
// swizzled smem; weights stream L2->smem (k64 chunks, 3-buffer single-barrier
// cp.async pipeline); ldmatrix fragments DOUBLE-BUFFERED in registers so LDSM
// latency overlaps the 16-MMA burst of the previous k-step.
// ============================================================================

#define D       256
#define FD      128
#define MTOT    16384
#define BHALF   8192
#define DT_MAG  0.1f
#define BM      128
#define NTH     512

// smem layout (bytes)
#define OFF_H   0                        // H tile: 128 rows x 512B, swizzled
#define OFF_G   65536                    // G tile; A bufs overlay in MODE 0
#define OFF_A0  65536                    // A staging: 3 x (128 x 128B)
#define OFF_B0  131072                   // B staging: 3 x (256 x 128B)
#define ABUF_SZ 16384
#define BBUF_SZ 32768
#define SMEM_TOTAL (131072 + 3 * BBUF_SZ)   // 229376

__device__ float         g_S [MTOT * D];
__device__ __nv_bfloat16 g_Sb[MTOT * D];
__device__ __nv_bfloat16 g_W1b [D * D];    // W1  [n][k]
__device__ __nv_bfloat16 g_W2b [D * D];    // W2  [n][k]
__device__ __nv_bfloat16 g_W1Tb[D * D];    // W1^T [n][k]
__device__ __nv_bfloat16 g_W2Tb[D * D];    // W2^T [n][k]

// ------------------------------- helpers ------------------------------------
__device__ __forceinline__ void cpa16(uint32_t dst, const void* src) {
    asm volatile("cp.async.cg.shared.global [%0], [%1], 16;"
                 :: "r"(dst), "l"(src) : "memory");
}
__device__ __forceinline__ uint32_t smem_u32(const void* p) {
    uint32_t r;
    asm("{ .reg .u64 t; cvta.to.shared.u64 t, %1; cvt.u32.u64 %0, t; }"
        : "=r"(r) : "l"(p));
    return r;
}
__device__ __forceinline__ void mma16(float* c, const uint32_t* a, const uint32_t* b) {
    asm volatile(
        "mma.sync.aligned.m16n8k16.row.col.f32.bf16.bf16.f32 "
        "{%0,%1,%2,%3}, {%4,%5,%6,%7}, {%8,%9}, {%0,%1,%2,%3};"
        : "+f"(c[0]), "+f"(c[1]), "+f"(c[2]), "+f"(c[3])
        : "r"(a[0]), "r"(a[1]), "r"(a[2]), "r"(a[3]), "r"(b[0]), "r"(b[1]));
}
#define LDMX4(r, addr) \
    asm volatile("ldmatrix.sync.aligned.m8n8.x4.shared.b16 {%0,%1,%2,%3}, [%4];" \
                 : "=r"((r)[0]), "=r"((r)[1]), "=r"((r)[2]), "=r"((r)[3]) \
                 : "r"(addr))
__device__ __forceinline__ uint32_t pk2(float x, float y) {
    __nv_bfloat162 h = __floats2bfloat162_rn(x, y);
    return *reinterpret_cast<uint32_t*>(&h);
}
__device__ __forceinline__ float2 up2(uint32_t u) {
    __nv_bfloat162 h = *reinterpret_cast<__nv_bfloat162*>(&u);
    return make_float2(__bfloat162float(h.x), __bfloat162float(h.y));
}
// tanh = 1 - 2/(1+e^{2x}); rcp via bit-trick + 2 Newton steps (FMA pipe)
__device__ __forceinline__ float ftanh(float x) {
    x = fminf(20.0f, fmaxf(-20.0f, x));
    float e;
    asm("ex2.approx.f32 %0, %1;" : "=f"(e) : "f"(x * 2.885390082f));
    float d = e + 1.0f;
    float y = __int_as_float(0x7EF311C3 - __float_as_int(d));
    y = y * (2.0f - d * y);
    y = y * (2.0f - d * y);
    return 1.0f - 2.0f * y;
}

// stage one k64 B chunk (rows x 128B) into a swizzled buffer; own group.
__device__ __forceinline__ void stageB_rows(uint32_t dst, const __nv_bfloat16* Bg0,
                                            int kc, int rows, int tid) {
    const __nv_bfloat16* Bg = Bg0 + kc * 64;
    const int n = rows >> 6;
    for (int i = 0; i < n; i++) {
        int idx = tid + (i << 9);
        int row = idx >> 3, c = idx & 7;
        cpa16(dst + row * 128 + ((c ^ (row & 7)) << 4),
              Bg + (size_t)row * D + c * 8);
    }
    asm volatile("cp.async.commit_group;" ::: "memory");
}

// --------------------------- prologue kernel --------------------------------
__global__ void prep_kernel(const float* __restrict__ W1,
                            const float* __restrict__ W2) {
    int idx = blockIdx.x * blockDim.x + threadIdx.x;
    int r = idx >> 8, c = idx & 255;
    __nv_bfloat16 v1 = __float2bfloat16(W1[idx]);
    __nv_bfloat16 v2 = __float2bfloat16(W2[idx]);
    g_W1b[idx] = v1;
    g_W2b[idx] = v2;
    g_W1Tb[c * D + r] = v1;
    g_W2Tb[c * D + r] = v2;
}

// ------------------------------ fused pass ----------------------------------
//  MODE 0: A = staged g_Sb, B = g_W1Tb -> H = tanh(acc + b1)
//  MODE 1: A = H tile,      B = g_W2Tb -> G = wout*(1 - tanh(acc+b2)^2)
//  MODE 2: A = G tile,      B = g_W2b  -> G = acc*(1 - H^2)   (in place)
//  MODE 3: A = G tile,      B = g_W1b  -> full kick (NT=8)
//  MODE 4: A = G tile,      B = g_W1b  -> half kick (NT=4)
template <int MODE, int NT>
__device__ __forceinline__ void pass_gemm(char* smem, uint32_t sbase,
                                          int m0, float dtv, int bs,
                                          const __nv_bfloat16* nextB, int nextRows,
                                          const float* __restrict__ b1g,
                                          const float* __restrict__ b2g,
                                          const float* __restrict__ wog) {
    const int tid  = threadIdx.x;
    const int wid  = tid >> 5;
    const int lane = tid & 31;
    const int g    = lane >> 2;
    const int t    = lane & 3;
    const int wm   = (wid & 3) * 32;
    const int wn   = (wid >> 2) * (NT * 8);
    const int NTOT = NT * 32;

    const uint32_t* Ht  = (const uint32_t*)(smem + OFF_H);
    uint32_t*       Htw = (uint32_t*)(smem + OFF_H);
    uint32_t*       Gt  = (uint32_t*)(smem + OFF_G);

    const __nv_bfloat16* Bsrc =
        (MODE == 0) ? g_W1Tb : (MODE == 1) ? g_W2Tb :
        (MODE == 2) ? g_W2b : g_W1b;

    const uint32_t Bbase = sbase + OFF_B0;
    const uint32_t Abase = sbase + OFF_A0;
    auto rotB = [&](uint32_t v) { return (v == Bbase + 2 * BBUF_SZ) ? Bbase : v + BBUF_SZ; };
    auto rotA = [&](uint32_t v) { return (v == Abase + 2 * ABUF_SZ) ? Abase : v + ABUF_SZ; };

    uint32_t curB = Bbase + (uint32_t)bs * BBUF_SZ;
    uint32_t curA = Abase + (uint32_t)bs * ABUF_SZ;
    uint32_t stgB = rotB(rotB(curB));
    uint32_t stgA = rotA(rotA(curA));

    auto stage = [&](int kc, uint32_t bdst, uint32_t adst) {
        const __nv_bfloat16* Bg = Bsrc + kc * 64;
#pragma unroll
        for (int i = 0; i < NTOT / 64; i++) {
            int idx = tid + (i << 9);
            int row = idx >> 3, c = idx & 7;
            cpa16(bdst + row * 128 + ((c ^ (row & 7)) << 4),
                  Bg + (size_t)row * D + c * 8);
        }
        if (MODE == 0) {
            const __nv_bfloat16* Ag = g_Sb + (size_t)m0 * D + kc * 64;
#pragma unroll
            for (int i = 0; i < 2; i++) {
                int idx = tid + (i << 9);
                int row = idx >> 3, c = idx & 7;
                cpa16(adst + row * 128 + ((c ^ (row & 7)) << 4),
                      Ag + (size_t)row * D + c * 8);
            }
        }
        asm volatile("cp.async.commit_group;" ::: "memory");
    };
    auto stageA1 = [&](int kc, uint32_t adst) {
        const __nv_bfloat16* Ag = g_Sb + (size_t)m0 * D + kc * 64;
#pragma unroll
        for (int i = 0; i < 2; i++) {
            int idx = tid + (i << 9);
            int row = idx >> 3, c = idx & 7;
            cpa16(adst + row * 128 + ((c ^ (row & 7)) << 4),
                  Ag + (size_t)row * D + c * 8);
        }
        asm volatile("cp.async.commit_group;" ::: "memory");
    };

    if (MODE == 0) {
        __syncthreads();                 // g_Sb writes -> cp.async; frees G
        stageA1(0, curA);
        stageA1(1, rotA(curA));
    }

    float acc[2][NT][4];
#pragma unroll
    for (int f = 0; f < 2; f++)
#pragma unroll
        for (int nf = 0; nf < NT; nf++)
#pragma unroll
            for (int r = 0; r < 4; r++) acc[f][nf][r] = 0.0f;

    // per-lane fragment address pieces
    const uint32_t aRowB = (uint32_t)(wm + (lane & 15)) * 128;
    const int      ax7   = lane & 7;
    const int      akh   = lane >> 4;
    const uint32_t bRowB =
        (uint32_t)(wn + ((lane >> 4) << 3) + (lane & 7)) * 128;
    const int      bx7   = (wn + ((lane >> 4) << 3) + (lane & 7)) & 7;
    const int      bkh   = (lane >> 3) & 1;
    const int hi4w = (lane >> 4) << 2;
    const int row7 = (lane & 7) << 2;
    uint32_t rrb[2];
#pragma unroll
    for (int f = 0; f < 2; f++)
        rrb[f] = sbase + ((MODE == 1) ? OFF_H : OFF_G) +
                 (uint32_t)(wm + f * 16 + (lane & 15)) * 512;

    // double-buffered fragment registers
    uint32_t afr[2][2][4], bfr[2][NT][2];

#pragma unroll 1
    for (int kc = 0; kc < 4; kc++) {
        if (kc < 3) asm volatile("cp.async.wait_group 1;" ::: "memory");
        else        asm volatile("cp.async.wait_group 0;" ::: "memory");
        __syncthreads();
        if (kc < 2) stage(kc + 2, stgB, stgA);

        const uint32_t aB = curA + aRowB;
        const uint32_t bB = curB + bRowB;

        // macro-ish fragment loader (buf/kk compile-time inside unrolled loop)
#define LOAD_FRAGS(BUF, KK)                                                   \
        do {                                                                  \
            if (MODE == 0) {                                                  \
                const uint32_t sa = (uint32_t)(((((KK) << 1) + akh) ^ ax7) << 4); \
                _Pragma("unroll")                                             \
                for (int f = 0; f < 2; f++) LDMX4(afr[BUF][f], aB + f * 2048 + sa); \
            } else {                                                          \
                const int kg_ = kc * 4 + (KK);                                \
                const uint32_t s4 = (uint32_t)((((kg_ << 3) + hi4w) ^ row7) << 2); \
                _Pragma("unroll")                                             \
                for (int f = 0; f < 2; f++) LDMX4(afr[BUF][f], rrb[f] + s4);  \
            }                                                                 \
            {                                                                 \
                const uint32_t sb4 = (uint32_t)(((((KK) << 1) + bkh) ^ bx7) << 4); \
                _Pragma("unroll")                                             \
                for (int j = 0; j < NT / 2; j++) {                            \
                    uint32_t r_[4];                                           \
                    LDMX4(r_, bB + j * 2048 + sb4);                           \
                    bfr[BUF][2*j][0]   = r_[0];  bfr[BUF][2*j][1]   = r_[1];  \
                    bfr[BUF][2*j+1][0] = r_[2];  bfr[BUF][2*j+1][1] = r_[3];  \
                }                                                             \
            }                                                                 \
        } while (0)

        LOAD_FRAGS(0, 0);
#pragma unroll
        for (int kk = 0; kk < 4; kk++) {
            const int cb = kk & 1;
            if (kk < 3) {
                if (cb) LOAD_FRAGS(0, kk + 1);
                else    LOAD_FRAGS(1, kk + 1);
            }
#pragma unroll
            for (int f = 0; f < 2; f++)
#pragma unroll
                for (int nf = 0; nf < NT; nf++)
                    mma16(acc[f][nf], afr[cb][f], bfr[cb][nf]);
        }
#undef LOAD_FRAGS

        curB = rotB(curB);  curA = rotA(curA);
        stgB = rotB(stgB);  stgA = rotA(stgA);
    }

    // cross-pass prefetch (bufs bs+1, bs+2 of next pass) — clobber-free
    if (nextB) {
        stageB_rows(curB, nextB, 0, nextRows, tid);
        stageB_rows(rotB(curB), nextB, 1, nextRows, tid);
    }
    if (MODE == 2) __syncthreads();   // in-place G overwrite: all reads done

    // ------------------------------ epilogue --------------------------------
#pragma unroll
    for (int f = 0; f < 2; f++) {
        const int r = wm + f * 16 + g;
#pragma unroll
        for (int nf = 0; nf < NT; nf++) {
            const int nc = wn + nf * 8 + 2 * t;
            const int ws = (nc >> 1) ^ (g << 2);
            float c0 = acc[f][nf][0], c1 = acc[f][nf][1];
            float c2 = acc[f][nf][2], c3 = acc[f][nf][3];

            if (MODE == 0) {
                float bv0 = __ldg(b1g + nc), bv1 = __ldg(b1g + nc + 1);
                Htw[r * 128 + ws]       = pk2(ftanh(c0 + bv0), ftanh(c1 + bv1));
                Htw[(r + 8) * 128 + ws] = pk2(ftanh(c2 + bv0), ftanh(c3 + bv1));
            } else if (MODE == 1) {
                float bv0 = __ldg(b2g + nc), bv1 = __ldg(b2g + nc + 1);
                float wv0 = __ldg(wog + nc), wv1 = __ldg(wog + nc + 1);
                float t0 = ftanh(c0 + bv0), t1 = ftanh(c1 + bv1);
                float t2 = ftanh(c2 + bv0), t3 = ftanh(c3 + bv1);
                Gt[r * 128 + ws]       = pk2(wv0 * (1.0f - t0 * t0),
                                             wv1 * (1.0f - t1 * t1));
                Gt[(r + 8) * 128 + ws] = pk2(wv0 * (1.0f - t2 * t2),
                                             wv1 * (1.0f - t3 * t3));
            } else if (MODE == 2) {
                float2 h0 = up2(Ht[r * 128 + ws]);
                float2 h1 = up2(Ht[(r + 8) * 128 + ws]);
                Gt[r * 128 + ws]       = pk2(c0 * (1.0f - h0.x * h0.x),
                                             c1 * (1.0f - h0.y * h0.y));
                Gt[(r + 8) * 128 + ws] = pk2(c2 * (1.0f - h1.x * h1.x),
                                             c3 * (1.0f - h1.y * h1.y));
            } else {
                const int grow = m0 + r;
                if (NT == 4 || nc < FD) {        // p -= 0.5*dt*dH[:, :FD]
                    float2* S0 = (float2*)(g_S + (size_t)grow * D + FD + nc);
                    float2* S1 = (float2*)(g_S + (size_t)(grow + 8) * D + FD + nc);
                    float2 p0 = *S0, p1 = *S1;
                    p0.x -= 0.5f * dtv * c0;  p0.y -= 0.5f * dtv * c1;
                    p1.x -= 0.5f * dtv * c2;  p1.y -= 0.5f * dtv * c3;
                    *S0 = p0;  *S1 = p1;
                    *(uint32_t*)(g_Sb + (size_t)grow * D + FD + nc)       = pk2(p0.x, p0.y);
                    *(uint32_t*)(g_Sb + (size_t)(grow + 8) * D + FD + nc) = pk2(p1.x, p1.y);
                } else {                          // q += dt*dH[:, FD:]
                    const int qc = nc - FD;
                    float2* S0 = (float2*)(g_S + (size_t)grow * D + qc);
                    float2* S1 = (float2*)(g_S + (size_t)(grow + 8) * D + qc);
                    float2 q0 = *S0, q1 = *S1;
                    q0.x += dtv * c0;  q0.y += dtv * c1;
                    q1.x += dtv * c2;  q1.y += dtv * c3;
                    *S0 = q0;  *S1 = q1;
                    *(uint32_t*)(g_Sb + (size_t)grow * D + qc)       = pk2(q0.x, q0.y);
                    *(uint32_t*)(g_Sb + (size_t)(grow + 8) * D + qc) = pk2(q1.x, q1.y);
                }
            }
        }
    }
}

// ------------------------------ fused kernel --------------------------------
__global__ void __launch_bounds__(NTH, 1)
fused_kernel(const float* __restrict__ b1, const float* __restrict__ b2,
             const float* __restrict__ wo, const float* __restrict__ x,
             float* __restrict__ out) {
    extern __shared__ __align__(1024) char smem[];
    const uint32_t sbase = smem_u32(smem);
    const int tid = threadIdx.x;
    const int m0  = blockIdx.x * BM;
    const int bwd = (m0 >= BHALF);
    const int b0  = m0 & (BHALF - 1);

    stageB_rows(sbase + OFF_B0, g_W1Tb, 0, 256, tid);
    stageB_rows(sbase + OFF_B0 + BBUF_SZ, g_W1Tb, 1, 256, tid);

    for (int i = tid; i < BM * 128; i += NTH) {
        int r = i >> 7, f = i & 127;
        size_t xb = (size_t)(b0 + r) * 8192;
        float xm  = x[xb + 4096 + f];
        float xm1 = x[xb + 3968 + f];
        float q = xm, p = xm - xm1;
        size_t srow = (size_t)(m0 + r) * D;
        g_S[srow + f]      = q;
        g_S[srow + FD + f] = p;
        g_Sb[srow + f]      = __float2bfloat16(q);
        g_Sb[srow + FD + f] = __float2bfloat16(p);
    }

    const float dtv = bwd ? -DT_MAG : DT_MAG;
    int bs = 0;
    auto inc = [&]() { bs = (bs == 2) ? 0 : bs + 1; };

#pragma unroll 1
    for (int it = 0; it < 8; it++) {
        pass_gemm<0, 8>(smem, sbase, m0, dtv, bs, g_W2Tb, 256, b1, b2, wo); inc();
        pass_gemm<1, 8>(smem, sbase, m0, dtv, bs, g_W2b, 256, b1, b2, wo);  inc();
        if ((it & 1) == 0) {
            pass_gemm<2, 8>(smem, sbase, m0, dtv, bs, g_W1b, 256, b1, b2, wo); inc();
            pass_gemm<3, 8>(smem, sbase, m0, dtv, bs, g_W1Tb, 256, b1, b2, wo); inc();
        } else {
            pass_gemm<2, 8>(smem, sbase, m0, dtv, bs, g_W1b, 128, b1, b2, wo); inc();
            if (it < 7) { pass_gemm<4, 4>(smem, sbase, m0, dtv, bs, g_W1Tb, 256, b1, b2, wo); }
            else        { pass_gemm<4, 4>(smem, sbase, m0, dtv, bs, nullptr, 0, b1, b2, wo); }
            inc();
        }
    }

    __syncthreads();
    for (int i = tid; i < BM * 64; i += NTH) {
        int r = i >> 6, c4 = i & 63;
        float4 v = *(const float4*)(g_S + (size_t)(m0 + r) * D + c4 * 4);
        float* orow = out + (size_t)(b0 + r) * 768;
        if (bwd) *(float4*)(orow + c4 * 4) = v;
        else     *(float4*)(orow + 512 + c4 * 4) = v;
    }
    if (!bwd) {
        for (int i = tid; i < BM * 128; i += NTH) {
            int r = i >> 7, f = i & 127;
            size_t xb = (size_t)(b0 + r) * 8192;
            float xm  = x[xb + 4096 + f];
            float xm1 = x[xb + 3968 + f];
            float* orow = out + (size_t)(b0 + r) * 768;
            orow[256 + f] = xm;
            orow[384 + f] = xm - xm1;
        }
    }
}

// ---------------------------------------------------------------------------
extern "C" void kernel_launch(void* const* d_in, const int* in_sizes, int n_in,
                              void* d_out, int out_size) {
    const float* x    = (const float*)d_in[0];
    const float* W1   = (const float*)d_in[1];
    const float* b1   = (const float*)d_in[2];
    const float* W2   = (const float*)d_in[3];
    const float* b2   = (const float*)d_in[4];
    const float* Wout = (const float*)d_in[5];
    float* out = (float*)d_out;

    cudaFuncSetAttribute(fused_kernel,
                         cudaFuncAttributeMaxDynamicSharedMemorySize, SMEM_TOTAL);

    prep_kernel<<<D * D / 256, 256>>>(W1, W2);
    fused_kernel<<<MTOT / BM, NTH, SMEM_TOTAL>>>(b1, b2, Wout, x, out);
}